// round 1
// baseline (speedup 1.0000x reference)
#include <cuda_runtime.h>
#include <cuda_bf16.h>
#include <cstdint>

#define SEQ   512
#define BATCH 64
#define DIM   1024
#define HID   1024
#define NJ    4096            // 4 gates * HID
#define MROWS (SEQ*BATCH)     // 32768

// ---------------- scratch (static device allocs only) ----------------
__device__ float g_G[(size_t)SEQ * BATCH * NJ];   // [t][b][j]  536 MB
__device__ float g_Wx[(size_t)DIM * NJ];          // [k][j] gate-concat
__device__ float g_Wh[(size_t)HID * NJ];          // [k][j] gate-concat
__device__ float g_bias[NJ];                      // bx+bh
__device__ unsigned int g_bar_count;
__device__ unsigned int g_bar_gen;

struct GatePtrs {
    const float* Wx[4];
    const float* Wh[4];
    const float* bx[4];
    const float* bh[4];
};

// ---------------- f32x2 helpers ----------------
__device__ __forceinline__ unsigned long long f2pack(float x, float y) {
    unsigned long long r;
    asm("mov.b64 %0, {%1, %2};" : "=l"(r) : "f"(x), "f"(y));
    return r;
}
__device__ __forceinline__ void f2unpack(unsigned long long v, float& x, float& y) {
    asm("mov.b64 {%0, %1}, %2;" : "=f"(x), "=f"(y) : "l"(v));
}
__device__ __forceinline__ unsigned long long f2fma(unsigned long long a,
                                                    unsigned long long b,
                                                    unsigned long long c) {
    unsigned long long d;
    asm("fma.rn.f32x2 %0, %1, %2, %3;" : "=l"(d) : "l"(a), "l"(b), "l"(c));
    return d;
}

// ---------------- kernel 1: repack weights/biases ----------------
__global__ void pack_kernel(GatePtrs p) {
    unsigned idx = blockIdx.x * blockDim.x + threadIdx.x;  // 0 .. DIM*NJ-1
    unsigned k = idx >> 12;        // / 4096
    unsigned j = idx & 4095;
    unsigned g = j >> 10;
    unsigned n = j & 1023;
    g_Wx[idx] = p.Wx[g][k * 1024u + n];
    g_Wh[idx] = p.Wh[g][k * 1024u + n];
    if (idx < NJ) g_bias[idx] = p.bx[g][n] + p.bh[g][n];
}

// ---------------- kernel 2: x-projection GEMM ----------------
// G[m][j] = x[m][:] @ g_Wx[:][j] + g_bias[j]   (m = t*64+b)
#define XBM 128
#define XBN 128
#define XBK 8

__global__ __launch_bounds__(256) void xproj_kernel(const float* __restrict__ x) {
    __shared__ float a_s[XBK][XBM + 2];   // [k][m], stride 130 (even)
    __shared__ float b_s[XBK][XBN];       // [k][n]

    const int tid = threadIdx.x;
    const int m0 = blockIdx.y * XBM;
    const int n0 = blockIdx.x * XBN;

    const int ty = tid >> 4;            // 0..15
    const int tx = tid & 15;            // 0..15
    const int m_loc = ty * 8;
    const int n_loc = tx * 8;

    unsigned long long acc[4][8];
#pragma unroll
    for (int p = 0; p < 4; p++)
#pragma unroll
        for (int i = 0; i < 8; i++) acc[p][i] = 0ull;

    const int a_m  = tid >> 1;          // 0..127
    const int a_k4 = (tid & 1) * 4;
    const int b_r  = tid >> 5;          // 0..7
    const int b_c4 = (tid & 31) * 4;

    for (int kt = 0; kt < DIM; kt += XBK) {
        float4 av = *(const float4*)(x + (size_t)(m0 + a_m) * DIM + kt + a_k4);
        a_s[a_k4 + 0][a_m] = av.x;
        a_s[a_k4 + 1][a_m] = av.y;
        a_s[a_k4 + 2][a_m] = av.z;
        a_s[a_k4 + 3][a_m] = av.w;
        float4 bv = *(const float4*)(g_Wx + (size_t)(kt + b_r) * NJ + n0 + b_c4);
        *(float4*)&b_s[b_r][b_c4] = bv;
        __syncthreads();

#pragma unroll
        for (int k = 0; k < XBK; k++) {
            unsigned long long ap[4];
#pragma unroll
            for (int p = 0; p < 4; p++)
                ap[p] = *(const unsigned long long*)&a_s[k][m_loc + 2 * p];
#pragma unroll
            for (int i = 0; i < 8; i++) {
                float bw = b_s[k][n_loc + i];
                unsigned long long bp = f2pack(bw, bw);
#pragma unroll
                for (int p = 0; p < 4; p++)
                    acc[p][i] = f2fma(ap[p], bp, acc[p][i]);
            }
        }
        __syncthreads();
    }

    // epilogue: add bias, write vectorized
    float bb[8];
#pragma unroll
    for (int i = 0; i < 8; i++) bb[i] = g_bias[n0 + n_loc + i];

#pragma unroll
    for (int p = 0; p < 4; p++) {
        float lo[8], hi[8];
#pragma unroll
        for (int i = 0; i < 8; i++) {
            f2unpack(acc[p][i], lo[i], hi[i]);
            lo[i] += bb[i];
            hi[i] += bb[i];
        }
        size_t base0 = (size_t)(m0 + m_loc + 2 * p) * NJ + n0 + n_loc;
        size_t base1 = base0 + NJ;
        *(float4*)(g_G + base0)     = make_float4(lo[0], lo[1], lo[2], lo[3]);
        *(float4*)(g_G + base0 + 4) = make_float4(lo[4], lo[5], lo[6], lo[7]);
        *(float4*)(g_G + base1)     = make_float4(hi[0], hi[1], hi[2], hi[3]);
        *(float4*)(g_G + base1 + 4) = make_float4(hi[4], hi[5], hi[6], hi[7]);
    }
}

// ---------------- kernel 3: persistent recurrence ----------------
#define RB  128    // grid blocks (<= 148 SMs -> co-resident, grid barrier is safe)
#define CPB 8      // hidden cols per block
#define RKT 64     // k-tile

__device__ __forceinline__ float sigm(float v) {
    return 1.0f / (1.0f + expf(-v));
}

__global__ __launch_bounds__(256) void lstm_steps_kernel(float* __restrict__ out) {
    __shared__ float h_s[RKT][66];       // [k][b], stride 66 (even, low-conflict)
    __shared__ float w_s[RKT][32];       // [k][col]
    __shared__ float pre_s[BATCH][33];   // [b][col]

    const int tid = threadIdx.x;
    const int n0 = blockIdx.x * CPB;

    // GEMM mapping: col -> (gate, local col); row-group -> 8 batch rows (4 pairs)
    const int col = tid & 31;
    const int jcol = (col >> 3) * HID + n0 + (col & 7);
    const int brow = (tid >> 5) * 8;

    // output mapping: thread owns (b0, b0+1) x column oc
    const int oc = tid & 7;
    const int b0 = (tid >> 3) * 2;

    float c0 = 0.0f, c1 = 0.0f;

    float* out_hseq = out;
    float* out_h = out + (size_t)SEQ * BATCH * HID;
    float* out_c = out_h + BATCH * HID;

    for (int t = 0; t < SEQ; t++) {
        unsigned long long acc[4] = {0ull, 0ull, 0ull, 0ull};

        if (t > 0) {
            const float* hprev = out_hseq + (size_t)(t - 1) * BATCH * HID;
            for (int kt = 0; kt < HID; kt += RKT) {
                // stage h tile transposed: h_s[k][b]   (L2 reads, L1-incoherent-safe)
#pragma unroll
                for (int l = 0; l < (RKT * BATCH) / 256; l++) {
                    int idx = tid + l * 256;
                    int b = idx >> 6;
                    int kk = idx & 63;
                    h_s[kk][b] = __ldcg(hprev + b * HID + kt + kk);
                }
                // stage w tile: w_s[k][col]
#pragma unroll
                for (int l = 0; l < (RKT * 32) / 256; l++) {
                    int idx = tid + l * 256;
                    int kk = idx >> 5;
                    int c = idx & 31;
                    int j = (c >> 3) * HID + n0 + (c & 7);
                    w_s[kk][c] = g_Wh[(size_t)(kt + kk) * NJ + j];
                }
                __syncthreads();
#pragma unroll
                for (int kk = 0; kk < RKT; kk++) {
                    float w = w_s[kk][col];
                    unsigned long long wp = f2pack(w, w);
#pragma unroll
                    for (int p = 0; p < 4; p++) {
                        unsigned long long hp =
                            *(const unsigned long long*)&h_s[kk][brow + 2 * p];
                        acc[p] = f2fma(hp, wp, acc[p]);
                    }
                }
                __syncthreads();
            }
        }

        // pre-activations = acc + G[t]   (G already holds x@Wx + bx + bh)
        {
            const float* Gt = g_G + (size_t)t * BATCH * NJ;
#pragma unroll
            for (int p = 0; p < 4; p++) {
                float lo, hi;
                f2unpack(acc[p], lo, hi);
                int b = brow + 2 * p;
                pre_s[b][col]     = lo + __ldg(Gt + (size_t)b * NJ + jcol);
                pre_s[b + 1][col] = hi + __ldg(Gt + (size_t)(b + 1) * NJ + jcol);
            }
        }
        __syncthreads();

        // gate math + state update (c lives in registers, owned per thread)
        {
            float fA = sigm(pre_s[b0][oc]);
            float iA = sigm(pre_s[b0][8 + oc]);
            float oA = sigm(pre_s[b0][16 + oc]);
            float gA = tanhf(pre_s[b0][24 + oc]);
            c0 = fA * c0 + iA * gA;
            float hA = oA * tanhf(c0);

            float fB = sigm(pre_s[b0 + 1][oc]);
            float iB = sigm(pre_s[b0 + 1][8 + oc]);
            float oB = sigm(pre_s[b0 + 1][16 + oc]);
            float gB = tanhf(pre_s[b0 + 1][24 + oc]);
            c1 = fB * c1 + iB * gB;
            float hB = oB * tanhf(c1);

            size_t idxA = (size_t)t * BATCH * HID + (size_t)b0 * HID + n0 + oc;
            size_t idxB = idxA + HID;
            out_hseq[idxA] = hA;
            out_hseq[idxB] = hB;
            if (t == SEQ - 1) {
                out_h[(size_t)b0 * HID + n0 + oc] = hA;
                out_h[(size_t)(b0 + 1) * HID + n0 + oc] = hB;
                out_c[(size_t)b0 * HID + n0 + oc] = c0;
                out_c[(size_t)(b0 + 1) * HID + n0 + oc] = c1;
            }
        }

        // grid barrier (skip after last step)
        if (t < SEQ - 1) {
            __threadfence();
            __syncthreads();
            if (tid == 0) {
                unsigned gen = atomicAdd(&g_bar_gen, 0u);
                unsigned arrived = atomicAdd(&g_bar_count, 1u);
                if (arrived == RB - 1) {
                    g_bar_count = 0u;
                    __threadfence();
                    atomicAdd(&g_bar_gen, 1u);
                } else {
                    while (atomicAdd(&g_bar_gen, 0u) == gen) { __nanosleep(64); }
                }
            }
            __syncthreads();
        }
    }
}

// ---------------- launch ----------------
extern "C" void kernel_launch(void* const* d_in, const int* in_sizes, int n_in,
                              void* d_out, int out_size) {
    const float* x = nullptr;
    const float* W[8] = {};
    const float* Bv[8] = {};
    int wi = 0, bi = 0;
    for (int i = 0; i < n_in; i++) {
        long long sz = in_sizes[i];
        if (sz == (long long)SEQ * BATCH * DIM) {
            x = (const float*)d_in[i];
        } else if (sz == (long long)DIM * HID) {
            if (wi < 8) W[wi++] = (const float*)d_in[i];
        } else if (sz == HID) {
            if (bi < 8) Bv[bi++] = (const float*)d_in[i];
        }
    }
    if (!x || wi != 8 || bi != 8) return;

    GatePtrs p;
    for (int g = 0; g < 4; g++) {
        p.Wx[g] = W[g];
        p.Wh[g] = W[4 + g];
        p.bx[g] = Bv[g];
        p.bh[g] = Bv[4 + g];
    }

    float* outf = (float*)d_out;

    pack_kernel<<<(DIM * NJ) / 1024, 1024>>>(p);

    dim3 xgrid(NJ / XBN, MROWS / XBM);   // (32, 256)
    xproj_kernel<<<xgrid, 256>>>(x);

    lstm_steps_kernel<<<RB, 256>>>(outf);
}